// round 2
// baseline (speedup 1.0000x reference)
#include <cuda_runtime.h>
#include <math.h>

#define NKEYS 131072
#define DDIM 128
#define MDIM 128
#define QDIM 512
#define KTOT 256          // concatenated K dimension: [d | m]
#define KB 16             // keys per preprocessing block

// Scratch (static device globals — no runtime allocation).
// g_B row n: [0:128) = vn * x_mse   ;  [128:256) = sign(proj) * vn * rn * sqrt(pi/2)/m
// g_A row q: [0:128) = query[q]     ;  [128:256) = Sq[q] = query[q] @ S^T
__device__ float g_B[(size_t)NKEYS * KTOT];   // 128 MB
__device__ float g_A[(size_t)QDIM * KTOT];    // 512 KB

// ---------------------------------------------------------------------------
// Kernel 1: build A = [query | query @ S^T]
// grid = (512), block = 128. Thread j computes Sq[q][j].
// ---------------------------------------------------------------------------
__global__ void build_A_kernel(const float* __restrict__ query,
                               const float* __restrict__ S) {
    __shared__ float qsh[DDIM];
    int q = blockIdx.x;
    int j = threadIdx.x;
    float qv = query[q * DDIM + j];
    qsh[j] = qv;
    __syncthreads();
    const float* Srow = S + j * DDIM;
    float acc = 0.f;
#pragma unroll 8
    for (int i = 0; i < DDIM; i++) acc += qsh[i] * Srow[i];
    g_A[(size_t)q * KTOT + j] = qv;
    g_A[(size_t)q * KTOT + DDIM + j] = acc;
}

// ---------------------------------------------------------------------------
// Kernel 2: per-key preprocessing → g_B
// block = 128 threads, KB=16 keys/block, grid = NKEYS/KB = 8192.
// S is staged transposed in shared (stride 132: float4-aligned, conflict-free
// reads). Each warp projects 4 keys: lane holds 4 consecutive j-outputs.
// ---------------------------------------------------------------------------
__global__ __launch_bounds__(128) void prep_keys_kernel(
    const float* __restrict__ keys, const float* __restrict__ codebook,
    const float* __restrict__ S) {
    extern __shared__ float sh[];
    float* St   = sh;                    // [128][132]  St[i*132+j] = S[j][i]
    float* rsh  = sh + 128 * 132;        // [KB][128]   residuals
    float* c2sh = rsh + KB * 128;        // [KB]        vn*rn*scale
    __shared__ float red[4];

    int tid  = threadIdx.x;
    int lane = tid & 31;
    int w    = tid >> 5;

    float c0 = codebook[0], c1 = codebook[1], c2v = codebook[2], c3 = codebook[3];
    float m01 = 0.5f * (c0 + c1), m12 = 0.5f * (c1 + c2v), m23 = 0.5f * (c2v + c3);

    // Stage S transposed (coalesced global reads).
    for (int idx = tid; idx < DDIM * MDIM; idx += 128) {
        int j = idx >> 7;
        int i = idx & 127;
        St[i * 132 + j] = S[idx];
    }

    size_t n0 = (size_t)blockIdx.x * KB;
    const float scale = 0.009797554543986288f;  // sqrt(pi/2) / 128

    for (int k = 0; k < KB; k++) {
        size_t n = n0 + (size_t)k;
        float kv = keys[n * DDIM + tid];

        float s = kv * kv;
#pragma unroll
        for (int o = 16; o; o >>= 1) s += __shfl_xor_sync(0xffffffffu, s, o);
        if (lane == 0) red[w] = s;
        __syncthreads();
        float vn = sqrtf(red[0] + red[1] + red[2] + red[3]);
        __syncthreads();

        float x  = kv / (vn + 1e-8f);
        // nearest of 4 sorted centers via midpoint compares
        float xm = (x >= m12) ? ((x >= m23) ? c3 : c2v)
                              : ((x >= m01) ? c1 : c0);
        float r = x - xm;

        float s2 = r * r;
#pragma unroll
        for (int o = 16; o; o >>= 1) s2 += __shfl_xor_sync(0xffffffffu, s2, o);
        if (lane == 0) red[w] = s2;
        __syncthreads();
        float rn = sqrtf(red[0] + red[1] + red[2] + red[3]);
        __syncthreads();

        g_B[n * KTOT + tid] = vn * xm;
        rsh[k * 128 + tid] = r;
        if (tid == 0) c2sh[k] = vn * rn * scale;
    }
    __syncthreads();

    // Projection: warp w handles keys [w*4, w*4+4); lane covers j = lane*4..+3.
    float acc[4][4];
#pragma unroll
    for (int a = 0; a < 4; a++)
#pragma unroll
        for (int b = 0; b < 4; b++) acc[a][b] = 0.f;

    int jb = lane * 4;
    const float* rbase = rsh + (w * 4) * 128;
#pragma unroll 4
    for (int i = 0; i < 128; i++) {
        float4 sv = *(const float4*)&St[i * 132 + jb];
#pragma unroll
        for (int kk = 0; kk < 4; kk++) {
            float rv = rbase[kk * 128 + i];   // broadcast LDS
            acc[kk][0] += sv.x * rv;
            acc[kk][1] += sv.y * rv;
            acc[kk][2] += sv.z * rv;
            acc[kk][3] += sv.w * rv;
        }
    }
#pragma unroll
    for (int kk = 0; kk < 4; kk++) {
        size_t n = n0 + (size_t)(w * 4 + kk);
        float cc = c2sh[w * 4 + kk];
        float4 o;
        o.x = (acc[kk][0] >= 0.f) ? cc : -cc;
        o.y = (acc[kk][1] >= 0.f) ? cc : -cc;
        o.z = (acc[kk][2] >= 0.f) ? cc : -cc;
        o.w = (acc[kk][3] >= 0.f) ? cc : -cc;
        *(float4*)&g_B[n * KTOT + DDIM + jb] = o;
    }
}

// ---------------------------------------------------------------------------
// Kernel 3: out(512 x 131072) = A(512x256) @ B(131072x256)^T, fp32
// 128x128x16 tiles, 256 threads, 8x8 micro-tiles. Shared stride 132 (pad).
// ---------------------------------------------------------------------------
#define BM 128
#define BN 128
#define BKC 16

__global__ __launch_bounds__(256) void gemm_kernel(float* __restrict__ out) {
    __shared__ float As[BKC][132];
    __shared__ float Bs[BKC][132];
    int tid = threadIdx.x;
    int tx = tid & 15;
    int ty = tid >> 4;
    size_t n0 = (size_t)blockIdx.x * BN;
    size_t q0 = (size_t)blockIdx.y * BM;
    const float* Aptr = g_A + q0 * KTOT;
    const float* Bptr = g_B + n0 * KTOT;

    float acc[8][8];
#pragma unroll
    for (int i = 0; i < 8; i++)
#pragma unroll
        for (int j = 0; j < 8; j++) acc[i][j] = 0.f;

    for (int k0 = 0; k0 < KTOT; k0 += BKC) {
#pragma unroll
        for (int it = 0; it < 2; it++) {
            int idx = tid + it * 256;        // 0..511 over (row, 4x float4)
            int row = idx >> 2;
            int c = (idx & 3) * 4;
            float4 a = *(const float4*)&Aptr[(size_t)row * KTOT + k0 + c];
            As[c + 0][row] = a.x; As[c + 1][row] = a.y;
            As[c + 2][row] = a.z; As[c + 3][row] = a.w;
            float4 b = *(const float4*)&Bptr[(size_t)row * KTOT + k0 + c];
            Bs[c + 0][row] = b.x; Bs[c + 1][row] = b.y;
            Bs[c + 2][row] = b.z; Bs[c + 3][row] = b.w;
        }
        __syncthreads();
#pragma unroll
        for (int kk = 0; kk < BKC; kk++) {
            float a[8], b[8];
            *(float4*)&a[0] = *(const float4*)&As[kk][ty * 8];
            *(float4*)&a[4] = *(const float4*)&As[kk][ty * 8 + 4];
            *(float4*)&b[0] = *(const float4*)&Bs[kk][tx * 8];
            *(float4*)&b[4] = *(const float4*)&Bs[kk][tx * 8 + 4];
#pragma unroll
            for (int i = 0; i < 8; i++)
#pragma unroll
                for (int j = 0; j < 8; j++)
                    acc[i][j] += a[i] * b[j];
        }
        __syncthreads();
    }

#pragma unroll
    for (int i = 0; i < 8; i++) {
        size_t row = q0 + (size_t)(ty * 8 + i);
        float* op = out + row * NKEYS + n0 + (size_t)(tx * 8);
        *(float4*)&op[0] = make_float4(acc[i][0], acc[i][1], acc[i][2], acc[i][3]);
        *(float4*)&op[4] = make_float4(acc[i][4], acc[i][5], acc[i][6], acc[i][7]);
    }
}

// ---------------------------------------------------------------------------
extern "C" void kernel_launch(void* const* d_in, const int* in_sizes, int n_in,
                              void* d_out, int out_size) {
    const float* query    = (const float*)d_in[0];
    const float* keys     = (const float*)d_in[1];
    const float* codebook = (const float*)d_in[2];
    const float* S        = (const float*)d_in[3];
    float* out = (float*)d_out;

    build_A_kernel<<<QDIM, 128>>>(query, S);

    size_t shbytes = (size_t)(128 * 132 + KB * 128 + KB) * sizeof(float);  // 75840 B
    cudaFuncSetAttribute(prep_keys_kernel,
                         cudaFuncAttributeMaxDynamicSharedMemorySize, (int)shbytes);
    prep_keys_kernel<<<NKEYS / KB, 128, shbytes>>>(keys, codebook, S);

    dim3 grid(NKEYS / BN, QDIM / BM);
    gemm_kernel<<<grid, 256>>>(out);
}